// round 16
// baseline (speedup 1.0000x reference)
#include <cuda_runtime.h>
#include <cuda_bf16.h>

// SIREN MLP fused kernel, fp32 + packed f32x2 FMAs (sm_103a).
// R5: conflict-free b layout (fixed R4's 8-way LDS conflict: 4590->3207us).
// R8: polynomial sine (Cody-Waite mod-pi + deg-11 Taylor), rel_err 1.15e-6.
// R9: b-operands via LDS.128 (column quads: half the LDS issue slots) and
//     double-buffered W staging (one barrier/stage instead of two).
//     R8 measured: L1=76.2%, fma=56.6%, issue=41.6% -> issue/stall-bound.

#define N_PTS   262144
#define HID     256
#define NL      4
#define TM      64
#define THREADS 256
#define OMEGA   30.0f

#define BK      16
#define NSTAGE  (HID / BK)

#define H_ELEMS   (TM * HID)            // 16384
#define W_ELEMS   (BK * HID)            // 4096 per buffer
#define SMEM_FLTS (H_ELEMS + 2 * W_ELEMS + 256)
#define SMEM_BYTES (SMEM_FLTS * 4)      // 99328 B -> 2 CTAs/SM

typedef unsigned long long ull;

__device__ __forceinline__ ull pack2(float lo) {
    ull r;
    asm("mov.b64 %0, {%1, %1};" : "=l"(r) : "f"(lo));
    return r;
}
__device__ __forceinline__ void unpack2(ull p, float& lo, float& hi) {
    asm("mov.b64 {%0, %1}, %2;" : "=f"(lo), "=f"(hi) : "l"(p));
}
__device__ __forceinline__ void fma2(ull& acc, ull a, ull b) {
    asm("fma.rn.f32x2 %0, %1, %2, %0;" : "+l"(acc) : "l"(a), "l"(b));
}

// sin(x) for |x| <= ~50: reduce mod pi (2-step Cody-Waite), deg-11 Taylor,
// sign flip by parity of k. Verified R8: end-to-end rel_err 1.145e-6.
__device__ __forceinline__ float fast_sin(float x) {
    const float k = rintf(x * 0.3183098861837907f);
    float r = fmaf(k, -3.14159274101257f, x);
    r = fmaf(k, 8.742277657347586e-8f, r);
    const float r2 = r * r;
    float p = fmaf(r2, -2.5052108e-8f, 2.7557319e-6f);
    p = fmaf(r2, p, -1.9841270e-4f);
    p = fmaf(r2, p, 8.3333333e-3f);
    p = fmaf(r2, p, -1.6666667e-1f);
    float s = fmaf(r2 * p, r, r);
    const int ki = (int)k;
    return __int_as_float(__float_as_int(s) ^ (ki << 31));
}

__global__ __launch_bounds__(THREADS, 2)
void siren_fused_kernel(const float* __restrict__ x,
                        const float* __restrict__ w_first,
                        const float* __restrict__ b_first,
                        const float* __restrict__ w_hidden,
                        const float* __restrict__ b_hidden,
                        const float* __restrict__ w_final,
                        const float* __restrict__ b_final,
                        float* __restrict__ out)
{
    extern __shared__ float smem[];
    float* h    = smem;                       // [TM][HID] canonical
    float* Wbuf = smem + H_ELEMS;             // 2 x [BK][HID] k-major
    float* xs   = smem + H_ELEMS + 2 * W_ELEMS;  // [TM][3]

    const int tid = threadIdx.x;
    const int p0  = blockIdx.x * TM;

    // ---- load x tile ----
    if (tid < TM * 3) xs[tid] = x[p0 * 3 + tid];
    __syncthreads();

    // ---- first layer: h = sin(30 * (x @ Wf^T + bf)) ----
    #pragma unroll 4
    for (int idx = tid; idx < TM * HID; idx += THREADS) {
        const int r = idx >> 8;
        const int c = idx & 255;
        float z = b_first[c];
        z = fmaf(w_first[c * 3 + 0], xs[r * 3 + 0], z);
        z = fmaf(w_first[c * 3 + 1], xs[r * 3 + 1], z);
        z = fmaf(w_first[c * 3 + 2], xs[r * 3 + 2], z);
        h[r * HID + c] = fast_sin(OMEGA * z);
    }

    // ---- hidden layers ----
    // Thread (ty,tx): rows [ty*8, ty*8+8); column QUADS [4tx,4tx+4) and
    // [128+4tx, 128+4tx+4). b-loads are lane-contiguous LDS.128.
    const int tx = tid & 31;
    const int ty = tid >> 5;
    const int r0 = ty * 8;

    for (int l = 0; l < NL; ++l) {
        const float* W = w_hidden + l * (HID * HID);
        const float* Wrow = W + tid * HID;   // thread stages out-row `tid`

        // acc[j*4+0..1]: col pairs (4tx,4tx+1),(4tx+2,4tx+3)
        // acc[j*4+2..3]: same at +128
        ull acc[32];
        {
            const ull* b64 = (const ull*)(b_hidden + l * HID);
            const ull bp0 = b64[2 * tx],      bp1 = b64[2 * tx + 1];
            const ull bp2 = b64[64 + 2 * tx], bp3 = b64[64 + 2 * tx + 1];
            #pragma unroll
            for (int j = 0; j < 8; ++j) {
                acc[j * 4 + 0] = bp0; acc[j * 4 + 1] = bp1;
                acc[j * 4 + 2] = bp2; acc[j * 4 + 3] = bp3;
            }
        }

        // prologue: stage 0 -> buf0
        float4 pre[4];
        #pragma unroll
        for (int q = 0; q < 4; ++q)
            pre[q] = *(const float4*)(Wrow + q * 4);
        #pragma unroll
        for (int q = 0; q < 4; ++q) {
            Wbuf[(q * 4 + 0) * HID + tid] = pre[q].x;
            Wbuf[(q * 4 + 1) * HID + tid] = pre[q].y;
            Wbuf[(q * 4 + 2) * HID + tid] = pre[q].z;
            Wbuf[(q * 4 + 3) * HID + tid] = pre[q].w;
        }
        __syncthreads();   // also orders h writes (first layer / prev epilogue)

        for (int s = 0; s < NSTAGE; ++s) {
            const float* cur = Wbuf + (s & 1) * W_ELEMS;
            // prefetch next stage from L2 (overlaps compute below)
            if (s + 1 < NSTAGE) {
                const int kn = (s + 1) * BK;
                #pragma unroll
                for (int q = 0; q < 4; ++q)
                    pre[q] = *(const float4*)(Wrow + kn + q * 4);
            }

            const int k0 = s * BK;
            #pragma unroll
            for (int kk = 0; kk < BK; kk += 2) {
                const ulonglong2* w0 = (const ulonglong2*)(cur + (kk + 0) * HID);
                const ulonglong2* w1 = (const ulonglong2*)(cur + (kk + 1) * HID);
                const ulonglong2 q00 = w0[tx];        // kk,   cols 4tx..4tx+3
                const ulonglong2 q01 = w0[tx + 32];   // kk,   cols 128+4tx..
                const ulonglong2 q10 = w1[tx];        // kk+1
                const ulonglong2 q11 = w1[tx + 32];
                const float* hk = h + k0 + kk;
                #pragma unroll
                for (int j = 0; j < 8; ++j) {
                    const float2 av = *(const float2*)(hk + (r0 + j) * HID);
                    const ull a0 = pack2(av.x);
                    const ull a1 = pack2(av.y);
                    fma2(acc[j * 4 + 0], a0, q00.x);
                    fma2(acc[j * 4 + 1], a0, q00.y);
                    fma2(acc[j * 4 + 2], a0, q01.x);
                    fma2(acc[j * 4 + 3], a0, q01.y);
                    fma2(acc[j * 4 + 0], a1, q10.x);
                    fma2(acc[j * 4 + 1], a1, q10.y);
                    fma2(acc[j * 4 + 2], a1, q11.x);
                    fma2(acc[j * 4 + 3], a1, q11.y);
                }
            }

            // stage s+1 into the other buffer (its last reader finished at
            // stage s-1, guaranteed by the barrier at end of stage s-1)
            if (s + 1 < NSTAGE) {
                float* nxt = Wbuf + ((s + 1) & 1) * W_ELEMS;
                #pragma unroll
                for (int q = 0; q < 4; ++q) {
                    nxt[(q * 4 + 0) * HID + tid] = pre[q].x;
                    nxt[(q * 4 + 1) * HID + tid] = pre[q].y;
                    nxt[(q * 4 + 2) * HID + tid] = pre[q].z;
                    nxt[(q * 4 + 3) * HID + tid] = pre[q].w;
                }
            }
            __syncthreads();   // one barrier per stage
        }

        // activation + in-place writeback (all h reads done: stage-15 barrier)
        #pragma unroll
        for (int j = 0; j < 8; ++j) {
            float* hrow = h + (r0 + j) * HID;
            float l0, h0, l1, h1;
            unpack2(acc[j * 4 + 0], l0, h0);
            unpack2(acc[j * 4 + 1], l1, h1);
            float4 v0;
            v0.x = fast_sin(OMEGA * l0); v0.y = fast_sin(OMEGA * h0);
            v0.z = fast_sin(OMEGA * l1); v0.w = fast_sin(OMEGA * h1);
            *(float4*)(hrow + 4 * tx) = v0;
            unpack2(acc[j * 4 + 2], l0, h0);
            unpack2(acc[j * 4 + 3], l1, h1);
            float4 v1;
            v1.x = fast_sin(OMEGA * l0); v1.y = fast_sin(OMEGA * h0);
            v1.z = fast_sin(OMEGA * l1); v1.w = fast_sin(OMEGA * h1);
            *(float4*)(hrow + 128 + 4 * tx) = v1;
        }
        __syncthreads();
    }

    // ---- final linear layer ----
    if (tid < TM * 3) {
        const int r = tid / 3;
        const int c = tid % 3;
        const float4* hrow = (const float4*)(h + r * HID);
        const float4* wrow = (const float4*)(w_final + c * HID);
        float a0 = 0.f, a1 = 0.f, a2s = 0.f, a3 = 0.f;
        #pragma unroll
        for (int q = 0; q < HID / 4; ++q) {
            const float4 hv = hrow[q];
            const float4 wv = wrow[q];
            a0 = fmaf(hv.x, wv.x, a0);
            a1 = fmaf(hv.y, wv.y, a1);
            a2s = fmaf(hv.z, wv.z, a2s);
            a3 = fmaf(hv.w, wv.w, a3);
        }
        out[(p0 + r) * 3 + c] = (a0 + a1) + (a2s + a3) + b_final[c];
    }
}

extern "C" void kernel_launch(void* const* d_in, const int* in_sizes, int n_in,
                              void* d_out, int out_size)
{
    const float* x        = (const float*)d_in[0];
    const float* w_first  = (const float*)d_in[1];
    const float* b_first  = (const float*)d_in[2];
    const float* w_hidden = (const float*)d_in[3];
    const float* b_hidden = (const float*)d_in[4];
    const float* w_final  = (const float*)d_in[5];
    const float* b_final  = (const float*)d_in[6];
    float* out = (float*)d_out;

    cudaFuncSetAttribute(siren_fused_kernel,
                         cudaFuncAttributeMaxDynamicSharedMemorySize, SMEM_BYTES);

    siren_fused_kernel<<<N_PTS / TM, THREADS, SMEM_BYTES>>>(
        x, w_first, b_first, w_hidden, b_hidden, w_final, b_final, out);
}